// round 1
// baseline (speedup 1.0000x reference)
#include <cuda_runtime.h>
#include <math.h>

#define F 256
#define N_MAX 65536

// Scratch (allocation-free rule: __device__ globals)
__device__ float g_deg[N_MAX];
__device__ float g_dinv[N_MAX];
__device__ float g_invdeg[N_MAX];
__device__ float g_agg[(size_t)N_MAX * F];
__device__ float g_X[(size_t)N_MAX * F];
__device__ float g_Weff[F * F];

// ---------------------------------------------------------------------------
// 0) zero agg + deg
__global__ void k_zero(int nf4, int n) {
    int i0 = blockIdx.x * blockDim.x + threadIdx.x;
    int stride = gridDim.x * blockDim.x;
    float4 z = make_float4(0.f, 0.f, 0.f, 0.f);
    float4* agg4 = reinterpret_cast<float4*>(g_agg);
    for (int i = i0; i < nf4; i += stride) agg4[i] = z;
    for (int i = i0; i < n; i += stride) g_deg[i] = 0.0f;
}

// ---------------------------------------------------------------------------
// 1) in-degree histogram over dst
__global__ void k_deg(const int* __restrict__ ei, int E) {
    int e = blockIdx.x * blockDim.x + threadIdx.x;
    if (e < E) atomicAdd(&g_deg[ei[E + e]], 1.0f);
}

// ---------------------------------------------------------------------------
// 2) per-node normalization terms
__global__ void k_node(int n) {
    int i = blockIdx.x * blockDim.x + threadIdx.x;
    if (i < n) {
        float d = g_deg[i] + 1.0f;
        g_dinv[i]   = rsqrtf(d);
        g_invdeg[i] = 1.0f / d;
    }
}

// ---------------------------------------------------------------------------
// 3) Weff = (1-beta)*I + beta*W   (folds the output mix into the GEMM)
__global__ void k_weff(const float* __restrict__ W,
                       const float* __restrict__ lamda_p,
                       const void* __restrict__ l_p) {
    float lam = __ldg(lamda_p);
    int   li  = reinterpret_cast<const int*>(l_p)[0];
    float lf  = (li > 0 && li < (1 << 20)) ? (float)li
                                           : reinterpret_cast<const float*>(l_p)[0];
    float beta = logf(lam / lf + 1.0f);
    int idx = blockIdx.x * blockDim.x + threadIdx.x;
    if (idx < F * F) {
        int r = idx / F, c = idx % F;
        g_Weff[idx] = beta * W[idx] + ((r == c) ? (1.0f - beta) : 0.0f);
    }
}

// ---------------------------------------------------------------------------
// 4) scatter: agg[src,:] += H[dst,:] * dinv[dst]  (one warp per edge)
__global__ void k_scatter(const float* __restrict__ H,
                          const int* __restrict__ ei, int E) {
    int gwarp = (blockIdx.x * blockDim.x + threadIdx.x) >> 5;
    int lane  = threadIdx.x & 31;
    if (gwarp >= E) return;
    int s = ei[gwarp];        // row of A (segment for agg)
    int d = ei[E + gwarp];    // col of A (gather row of H)
    float w = __ldg(&g_dinv[d]);
    const float4* hrow = reinterpret_cast<const float4*>(H + (size_t)d * F);
    float4* arow = reinterpret_cast<float4*>(g_agg + (size_t)s * F);
#pragma unroll
    for (int c = lane; c < F / 4; c += 32) {
        float4 v = __ldg(&hrow[c]);
        v.x *= w; v.y *= w; v.z *= w; v.w *= w;
#if __CUDA_ARCH__ >= 900
        atomicAdd(&arow[c], v);   // RED.v4.f32
#else
        float* a = reinterpret_cast<float*>(&arow[c]);
        atomicAdd(a + 0, v.x); atomicAdd(a + 1, v.y);
        atomicAdd(a + 2, v.z); atomicAdd(a + 3, v.w);
#endif
    }
}

// ---------------------------------------------------------------------------
// 5) X = (1-alpha)*(dinv*agg + H/deg) + alpha*H0
__global__ void k_init(const float* __restrict__ H,
                       const float* __restrict__ H0,
                       const float* __restrict__ alpha_p, int n) {
    int idx = blockIdx.x * blockDim.x + threadIdx.x;
    int total = n * (F / 4);
    if (idx >= total) return;
    int row = idx / (F / 4);
    float a  = __ldg(alpha_p);
    float oa = 1.0f - a;
    float di = g_dinv[row];
    float id = g_invdeg[row];
    float4 hg = reinterpret_cast<const float4*>(H)[idx];
    float4 ag = reinterpret_cast<const float4*>(g_agg)[idx];
    float4 h0 = reinterpret_cast<const float4*>(H0)[idx];
    float4 r;
    r.x = oa * (di * ag.x + hg.x * id) + a * h0.x;
    r.y = oa * (di * ag.y + hg.y * id) + a * h0.y;
    r.z = oa * (di * ag.z + hg.z * id) + a * h0.z;
    r.w = oa * (di * ag.w + hg.w * id) + a * h0.w;
    reinterpret_cast<float4*>(g_X)[idx] = r;
}

// ---------------------------------------------------------------------------
// 6) out = X @ Weff      (M x 256) @ (256 x 256)
//    BM=64, BN=256, BK=32, 256 threads, 8x8 register tile per thread
__global__ __launch_bounds__(256, 2)
void k_gemm(float* __restrict__ out, int M) {
    __shared__ float Xs[64][32];   //  8 KB
    __shared__ float Ws[32][256];  // 32 KB

    const int tid = threadIdx.x;
    const int tn = tid & 31;   // 32 column groups of 8
    const int tm = tid >> 5;   //  8 row groups of 8
    const int block_row = blockIdx.x * 64;

    float acc[8][8];
#pragma unroll
    for (int i = 0; i < 8; i++)
#pragma unroll
        for (int j = 0; j < 8; j++) acc[i][j] = 0.0f;

    for (int k0 = 0; k0 < F; k0 += 32) {
        // load X tile: 64x32 floats = 512 float4, 2 per thread
#pragma unroll
        for (int i = tid; i < 64 * 8; i += 256) {
            int r = i >> 3;          // row in tile
            int c4 = i & 7;          // float4 col
            int grow = block_row + r;
            float4 v = make_float4(0.f, 0.f, 0.f, 0.f);
            if (grow < M)
                v = reinterpret_cast<const float4*>(g_X + (size_t)grow * F + k0)[c4];
            reinterpret_cast<float4*>(&Xs[r][0])[c4] = v;
        }
        // load W tile: 32x256 floats = 2048 float4, 8 per thread
#pragma unroll
        for (int i = tid; i < 32 * 64; i += 256) {
            int r = i >> 6;          // k row
            int c4 = i & 63;         // float4 col
            float4 v = reinterpret_cast<const float4*>(g_Weff + (size_t)(k0 + r) * F)[c4];
            reinterpret_cast<float4*>(&Ws[r][0])[c4] = v;
        }
        __syncthreads();

#pragma unroll
        for (int kk = 0; kk < 32; kk++) {
            float a[8];
#pragma unroll
            for (int i = 0; i < 8; i++) a[i] = Xs[tm * 8 + i][kk];
            float4 b0 = *reinterpret_cast<const float4*>(&Ws[kk][tn * 8]);
            float4 b1 = *reinterpret_cast<const float4*>(&Ws[kk][tn * 8 + 4]);
            float b[8] = {b0.x, b0.y, b0.z, b0.w, b1.x, b1.y, b1.z, b1.w};
#pragma unroll
            for (int i = 0; i < 8; i++)
#pragma unroll
                for (int j = 0; j < 8; j++) acc[i][j] += a[i] * b[j];
        }
        __syncthreads();
    }

#pragma unroll
    for (int i = 0; i < 8; i++) {
        int grow = block_row + tm * 8 + i;
        if (grow >= M) continue;
        float4 o0 = make_float4(acc[i][0], acc[i][1], acc[i][2], acc[i][3]);
        float4 o1 = make_float4(acc[i][4], acc[i][5], acc[i][6], acc[i][7]);
        float4* orow = reinterpret_cast<float4*>(out + (size_t)grow * F);
        orow[tn * 2 + 0] = o0;
        orow[tn * 2 + 1] = o1;
    }
}

// ---------------------------------------------------------------------------
extern "C" void kernel_launch(void* const* d_in, const int* in_sizes, int n_in,
                              void* d_out, int out_size) {
    const float* H     = (const float*)d_in[0];
    const int*   ei    = (const int*)d_in[1];
    const float* H0    = (const float*)d_in[2];
    const float* W     = (const float*)d_in[3];
    const float* lamda = (const float*)d_in[4];
    const float* alpha = (const float*)d_in[5];
    const void*  lp    = d_in[6];
    float* out = (float*)d_out;

    const int n  = in_sizes[0] / F;   // 50000
    const int E  = in_sizes[1] / 2;   // 800000
    const int nf4 = n * (F / 4);

    k_zero<<<2048, 256>>>(nf4, n);
    k_deg<<<(E + 255) / 256, 256>>>(ei, E);
    k_node<<<(n + 255) / 256, 256>>>(n);
    k_weff<<<(F * F + 255) / 256, 256>>>(W, lamda, lp);

    long long scatter_threads = (long long)E * 32;
    int scatter_blocks = (int)((scatter_threads + 255) / 256);
    k_scatter<<<scatter_blocks, 256>>>(H, ei, E);

    k_init<<<(nf4 + 255) / 256, 256>>>(H, H0, alpha, n);
    k_gemm<<<(n + 63) / 64, 256>>>(out, n);
}

// round 2
// speedup vs baseline: 1.3856x; 1.3856x over previous
#include <cuda_runtime.h>
#include <math.h>
#include <stdint.h>

#define F 256
#define N_MAX 65536

// Scratch (allocation-free rule: __device__ globals)
__device__ float g_deg[N_MAX];
__device__ float g_dinv[N_MAX];
__device__ float g_invdeg[N_MAX];
__device__ float g_agg[(size_t)N_MAX * F];
__device__ float g_X[(size_t)N_MAX * F];

// ---------------------------------------------------------------------------
// 0) zero agg + deg
__global__ void k_zero(int nf4, int n) {
    int i0 = blockIdx.x * blockDim.x + threadIdx.x;
    int stride = gridDim.x * blockDim.x;
    float4 z = make_float4(0.f, 0.f, 0.f, 0.f);
    float4* agg4 = reinterpret_cast<float4*>(g_agg);
    for (int i = i0; i < nf4; i += stride) agg4[i] = z;
    for (int i = i0; i < n; i += stride) g_deg[i] = 0.0f;
}

// ---------------------------------------------------------------------------
// 1) in-degree histogram over dst
__global__ void k_deg(const int* __restrict__ ei, int E) {
    int e = blockIdx.x * blockDim.x + threadIdx.x;
    if (e < E) atomicAdd(&g_deg[ei[E + e]], 1.0f);
}

// ---------------------------------------------------------------------------
// 2) per-node normalization terms
__global__ void k_node(int n) {
    int i = blockIdx.x * blockDim.x + threadIdx.x;
    if (i < n) {
        float d = g_deg[i] + 1.0f;
        g_dinv[i]   = rsqrtf(d);
        g_invdeg[i] = 1.0f / d;
    }
}

// ---------------------------------------------------------------------------
// 3) scatter: agg[src,:] += H[dst,:] * dinv[dst]  (one warp per edge)
__global__ void k_scatter(const float* __restrict__ H,
                          const int* __restrict__ ei, int E) {
    int gwarp = (blockIdx.x * blockDim.x + threadIdx.x) >> 5;
    int lane  = threadIdx.x & 31;
    if (gwarp >= E) return;
    int s = ei[gwarp];        // row of A (segment for agg)
    int d = ei[E + gwarp];    // col of A (gather row of H)
    float w = __ldg(&g_dinv[d]);
    const float4* hrow = reinterpret_cast<const float4*>(H + (size_t)d * F);
    float4* arow = reinterpret_cast<float4*>(g_agg + (size_t)s * F);
#pragma unroll
    for (int c = lane; c < F / 4; c += 32) {
        float4 v = __ldg(&hrow[c]);
        v.x *= w; v.y *= w; v.z *= w; v.w *= w;
#if __CUDA_ARCH__ >= 900
        atomicAdd(&arow[c], v);   // RED.v4.f32
#else
        float* a = reinterpret_cast<float*>(&arow[c]);
        atomicAdd(a + 0, v.x); atomicAdd(a + 1, v.y);
        atomicAdd(a + 2, v.z); atomicAdd(a + 3, v.w);
#endif
    }
}

// ---------------------------------------------------------------------------
// 4) X = (1-alpha)*(dinv*agg + H/deg) + alpha*H0
__global__ void k_init(const float* __restrict__ H,
                       const float* __restrict__ H0,
                       const float* __restrict__ alpha_p, int n) {
    int idx = blockIdx.x * blockDim.x + threadIdx.x;
    int total = n * (F / 4);
    if (idx >= total) return;
    int row = idx / (F / 4);
    float a  = __ldg(alpha_p);
    float oa = 1.0f - a;
    float di = g_dinv[row];
    float id = g_invdeg[row];
    float4 hg = reinterpret_cast<const float4*>(H)[idx];
    float4 ag = reinterpret_cast<const float4*>(g_agg)[idx];
    float4 h0 = reinterpret_cast<const float4*>(H0)[idx];
    float4 r;
    r.x = oa * (di * ag.x + hg.x * id) + a * h0.x;
    r.y = oa * (di * ag.y + hg.y * id) + a * h0.y;
    r.z = oa * (di * ag.z + hg.z * id) + a * h0.z;
    r.w = oa * (di * ag.w + hg.w * id) + a * h0.w;
    reinterpret_cast<float4*>(g_X)[idx] = r;
}

// ---------------------------------------------------------------------------
// 5) out = (1-beta)*X + beta*(X @ W)   -- tf32 tensor-core GEMM for X@W only,
//    the dominant (1-beta)*X term stays full fp32 in the epilogue.
//    Block 128x128, 8 warps (4M x 2N), warp tile 32x64, BK=32.
__global__ __launch_bounds__(256, 2)
void k_gemm_tf32(const float* __restrict__ W,
                 float* __restrict__ out,
                 const float* __restrict__ lamda_p,
                 const void* __restrict__ l_p, int M)
{
    __shared__ float Xs[128][36];   // 18 KB, stride 36 -> conflict-free frags
    __shared__ float Bs[32][132];   // 16.9 KB, stride 132 -> conflict-free

    const int tid   = threadIdx.x;
    const int warp  = tid >> 5;
    const int lane  = tid & 31;
    const int gid   = lane >> 2;    // 0..7
    const int ln4   = lane & 3;     // 0..3
    const int warpM = warp & 3;     // 0..3
    const int warpN = warp >> 2;    // 0..1
    const int blockRow = blockIdx.x * 128;
    const int blockCol = blockIdx.y * 128;

    float acc[2][8][4];
#pragma unroll
    for (int a = 0; a < 2; a++)
#pragma unroll
        for (int b = 0; b < 8; b++)
#pragma unroll
            for (int c = 0; c < 4; c++) acc[a][b][c] = 0.0f;

    for (int k0 = 0; k0 < F; k0 += 32) {
        // A tile: 128x32 (1024 float4, 4 per thread)
#pragma unroll
        for (int i = 0; i < 4; i++) {
            int idx = tid + i * 256;
            int r = idx >> 3, c4 = idx & 7;
            int grow = blockRow + r;
            float4 v = make_float4(0.f, 0.f, 0.f, 0.f);
            if (grow < M)
                v = *reinterpret_cast<const float4*>(&g_X[(size_t)grow * F + k0 + c4 * 4]);
            *reinterpret_cast<float4*>(&Xs[r][c4 * 4]) = v;
        }
        // B tile: 32x128 from W (row-major K x N)
#pragma unroll
        for (int i = 0; i < 4; i++) {
            int idx = tid + i * 256;
            int r = idx >> 5, c4 = idx & 31;
            float4 v = *reinterpret_cast<const float4*>(
                &W[(size_t)(k0 + r) * F + blockCol + c4 * 4]);
            *reinterpret_cast<float4*>(&Bs[r][c4 * 4]) = v;
        }
        __syncthreads();

#pragma unroll
        for (int ks = 0; ks < 32; ks += 8) {
            uint32_t afr[2][4];
#pragma unroll
            for (int mt = 0; mt < 2; mt++) {
                int r0 = warpM * 32 + mt * 16 + gid;
                afr[mt][0] = __float_as_uint(Xs[r0][ks + ln4]);
                afr[mt][1] = __float_as_uint(Xs[r0 + 8][ks + ln4]);
                afr[mt][2] = __float_as_uint(Xs[r0][ks + ln4 + 4]);
                afr[mt][3] = __float_as_uint(Xs[r0 + 8][ks + ln4 + 4]);
            }
#pragma unroll
            for (int nt = 0; nt < 8; nt++) {
                int c0 = warpN * 64 + nt * 8 + gid;
                uint32_t b0 = __float_as_uint(Bs[ks + ln4][c0]);
                uint32_t b1 = __float_as_uint(Bs[ks + ln4 + 4][c0]);
#pragma unroll
                for (int mt = 0; mt < 2; mt++) {
                    asm volatile(
                        "mma.sync.aligned.m16n8k8.row.col.f32.tf32.tf32.f32 "
                        "{%0,%1,%2,%3}, {%4,%5,%6,%7}, {%8,%9}, {%0,%1,%2,%3};\n"
                        : "+f"(acc[mt][nt][0]), "+f"(acc[mt][nt][1]),
                          "+f"(acc[mt][nt][2]), "+f"(acc[mt][nt][3])
                        : "r"(afr[mt][0]), "r"(afr[mt][1]),
                          "r"(afr[mt][2]), "r"(afr[mt][3]),
                          "r"(b0), "r"(b1));
                }
            }
        }
        __syncthreads();
    }

    // epilogue: out = (1-beta)*X (fp32) + beta*acc
    float lam = __ldg(lamda_p);
    int   li  = *reinterpret_cast<const int*>(l_p);
    float lf  = (li > 0 && li < (1 << 20)) ? (float)li
                                           : *reinterpret_cast<const float*>(l_p);
    float beta = logf(lam / lf + 1.0f);
    float ob   = 1.0f - beta;

#pragma unroll
    for (int mt = 0; mt < 2; mt++) {
#pragma unroll
        for (int half = 0; half < 2; half++) {
            int row = blockRow + warpM * 32 + mt * 16 + gid + half * 8;
            if (row >= M) continue;
#pragma unroll
            for (int nt = 0; nt < 8; nt++) {
                int col = blockCol + warpN * 64 + nt * 8 + 2 * ln4;
                float2 xv = *reinterpret_cast<const float2*>(&g_X[(size_t)row * F + col]);
                float2 o;
                o.x = ob * xv.x + beta * acc[mt][nt][half * 2 + 0];
                o.y = ob * xv.y + beta * acc[mt][nt][half * 2 + 1];
                *reinterpret_cast<float2*>(&out[(size_t)row * F + col]) = o;
            }
        }
    }
}

// ---------------------------------------------------------------------------
extern "C" void kernel_launch(void* const* d_in, const int* in_sizes, int n_in,
                              void* d_out, int out_size) {
    const float* H     = (const float*)d_in[0];
    const int*   ei    = (const int*)d_in[1];
    const float* H0    = (const float*)d_in[2];
    const float* W     = (const float*)d_in[3];
    const float* lamda = (const float*)d_in[4];
    const float* alpha = (const float*)d_in[5];
    const void*  lp    = d_in[6];
    float* out = (float*)d_out;

    const int n   = in_sizes[0] / F;   // 50000
    const int E   = in_sizes[1] / 2;   // 800000
    const int nf4 = n * (F / 4);

    k_zero<<<2048, 256>>>(nf4, n);
    k_deg<<<(E + 255) / 256, 256>>>(ei, E);
    k_node<<<(n + 255) / 256, 256>>>(n);

    long long scatter_threads = (long long)E * 32;
    int scatter_blocks = (int)((scatter_threads + 255) / 256);
    k_scatter<<<scatter_blocks, 256>>>(H, ei, E);

    k_init<<<(nf4 + 255) / 256, 256>>>(H, H0, alpha, n);

    dim3 grid((n + 127) / 128, 2);
    k_gemm_tf32<<<grid, 256>>>(W, out, lamda, lp, n);
}

// round 3
// speedup vs baseline: 1.9777x; 1.4274x over previous
#include <cuda_runtime.h>
#include <math.h>
#include <stdint.h>

#define F 256
#define N_MAX 65536
#define E_CAP (1 << 20)
#define SCAN_CHUNK 2048

// Scratch (allocation-free rule: __device__ globals)
__device__ int   g_cnt[N_MAX];      // out-count per src (CSR)
__device__ int   g_degi[N_MAX];     // in-count per dst
__device__ int   g_off[N_MAX];      // CSR row offsets (exclusive scan of cnt)
__device__ int   g_cursor[N_MAX];   // fill cursors
__device__ int   g_partial[64];     // scan block totals
__device__ int   g_partial2[64];    // scanned (exclusive) block totals
__device__ int   g_edst[E_CAP];     // CSR column (dst) indices
__device__ float g_dinv[N_MAX];
__device__ float g_invdeg[N_MAX];
__device__ float g_X[(size_t)N_MAX * F];

// ---------------------------------------------------------------------------
// 0) zero counters
__global__ void k_zero(int n) {
    int i = blockIdx.x * blockDim.x + threadIdx.x;
    if (i < n) { g_cnt[i] = 0; g_degi[i] = 0; g_cursor[i] = 0; }
}

// ---------------------------------------------------------------------------
// 1) histogram: out-count by src, in-count by dst (one edge pass)
__global__ void k_count(const int* __restrict__ ei, int E) {
    int e = blockIdx.x * blockDim.x + threadIdx.x;
    if (e < E) {
        atomicAdd(&g_cnt[ei[e]], 1);
        atomicAdd(&g_degi[ei[E + e]], 1);
    }
}

// ---------------------------------------------------------------------------
// 2) exclusive scan of g_cnt -> g_off   (chunks of 2048)
__global__ void k_scan1(int n) {
    const int tid = threadIdx.x;
    const int base = blockIdx.x * SCAN_CHUNK;
    int v[8]; int s = 0;
#pragma unroll
    for (int j = 0; j < 8; j++) {
        int idx = base + tid * 8 + j;
        int c = (idx < n) ? g_cnt[idx] : 0;
        v[j] = s; s += c;
    }
    __shared__ int sh[256];
    sh[tid] = s;
    __syncthreads();
    for (int o = 1; o < 256; o <<= 1) {
        int t = (tid >= o) ? sh[tid - o] : 0;
        __syncthreads();
        sh[tid] += t;
        __syncthreads();
    }
    int excl = sh[tid] - s;
#pragma unroll
    for (int j = 0; j < 8; j++) {
        int idx = base + tid * 8 + j;
        if (idx < n) g_off[idx] = excl + v[j];
    }
    if (tid == 255) g_partial[blockIdx.x] = sh[255];
}

__global__ void k_scan2(int nb) {   // nb <= 32 for N_MAX=65536
    int tid = threadIdx.x;
    int orig = (tid < nb) ? g_partial[tid] : 0;
    int x = orig;
#pragma unroll
    for (int o = 1; o < 32; o <<= 1) {
        int y = __shfl_up_sync(0xffffffffu, x, o);
        if (tid >= o) x += y;
    }
    if (tid < nb) g_partial2[tid] = x - orig;  // exclusive
}

__global__ void k_scan3(int n) {
    int i = blockIdx.x * blockDim.x + threadIdx.x;
    if (i < n) g_off[i] += g_partial2[i / SCAN_CHUNK];
}

// ---------------------------------------------------------------------------
// 3) per-node normalization terms
__global__ void k_node(int n) {
    int i = blockIdx.x * blockDim.x + threadIdx.x;
    if (i < n) {
        float d = (float)g_degi[i] + 1.0f;
        g_dinv[i]   = rsqrtf(d);
        g_invdeg[i] = 1.0f / d;
    }
}

// ---------------------------------------------------------------------------
// 4) CSR fill: bucket dst by src
__global__ void k_fill(const int* __restrict__ ei, int E) {
    int e = blockIdx.x * blockDim.x + threadIdx.x;
    if (e < E) {
        int s = ei[e];
        int pos = atomicAdd(&g_cursor[s], 1);
        g_edst[g_off[s] + pos] = ei[E + e];
    }
}

// ---------------------------------------------------------------------------
// 5) fused aggregate + init: one warp per node, no atomics.
//    X[i] = (1-a)*(dinv[i]*sum_j H[j]*dinv[j] + H[i]*invdeg[i]) + a*H0[i]
__global__ __launch_bounds__(256)
void k_agg(const float* __restrict__ H,
           const float* __restrict__ H0,
           const float* __restrict__ alpha_p, int n)
{
    int warp = (blockIdx.x * blockDim.x + threadIdx.x) >> 5;
    int lane = threadIdx.x & 31;
    if (warp >= n) return;
    const int i    = warp;
    const int base = g_off[i];
    const int cnt  = g_cnt[i];

    const float4* H4 = reinterpret_cast<const float4*>(H);
    float4 acc0 = make_float4(0.f, 0.f, 0.f, 0.f);
    float4 acc1 = make_float4(0.f, 0.f, 0.f, 0.f);

    int e = 0;
    for (; e + 2 <= cnt; e += 2) {
        int d0 = __ldg(&g_edst[base + e]);
        int d1 = __ldg(&g_edst[base + e + 1]);
        float w0 = __ldg(&g_dinv[d0]);
        float w1 = __ldg(&g_dinv[d1]);
        const float4* p0 = H4 + (size_t)d0 * (F / 4) + lane * 2;
        const float4* p1 = H4 + (size_t)d1 * (F / 4) + lane * 2;
        float4 a0 = __ldg(p0), a1 = __ldg(p0 + 1);
        float4 b0 = __ldg(p1), b1 = __ldg(p1 + 1);
        acc0.x += a0.x * w0 + b0.x * w1;
        acc0.y += a0.y * w0 + b0.y * w1;
        acc0.z += a0.z * w0 + b0.z * w1;
        acc0.w += a0.w * w0 + b0.w * w1;
        acc1.x += a1.x * w0 + b1.x * w1;
        acc1.y += a1.y * w0 + b1.y * w1;
        acc1.z += a1.z * w0 + b1.z * w1;
        acc1.w += a1.w * w0 + b1.w * w1;
    }
    if (e < cnt) {
        int d0 = __ldg(&g_edst[base + e]);
        float w0 = __ldg(&g_dinv[d0]);
        const float4* p0 = H4 + (size_t)d0 * (F / 4) + lane * 2;
        float4 a0 = __ldg(p0), a1 = __ldg(p0 + 1);
        acc0.x += a0.x * w0; acc0.y += a0.y * w0;
        acc0.z += a0.z * w0; acc0.w += a0.w * w0;
        acc1.x += a1.x * w0; acc1.y += a1.y * w0;
        acc1.z += a1.z * w0; acc1.w += a1.w * w0;
    }

    // epilogue
    float a  = __ldg(alpha_p);
    float oa = 1.0f - a;
    float di = g_dinv[i];
    float id = g_invdeg[i];
    size_t ro = (size_t)i * (F / 4) + lane * 2;
    float4 h0  = __ldg(H4 + ro);
    float4 h1  = __ldg(H4 + ro + 1);
    const float4* H04 = reinterpret_cast<const float4*>(H0);
    float4 z0 = __ldg(H04 + ro);
    float4 z1 = __ldg(H04 + ro + 1);
    float4 r0, r1;
    r0.x = oa * (di * acc0.x + h0.x * id) + a * z0.x;
    r0.y = oa * (di * acc0.y + h0.y * id) + a * z0.y;
    r0.z = oa * (di * acc0.z + h0.z * id) + a * z0.z;
    r0.w = oa * (di * acc0.w + h0.w * id) + a * z0.w;
    r1.x = oa * (di * acc1.x + h1.x * id) + a * z1.x;
    r1.y = oa * (di * acc1.y + h1.y * id) + a * z1.y;
    r1.z = oa * (di * acc1.z + h1.z * id) + a * z1.z;
    r1.w = oa * (di * acc1.w + h1.w * id) + a * z1.w;
    float4* X4 = reinterpret_cast<float4*>(g_X);
    X4[ro]     = r0;
    X4[ro + 1] = r1;
}

// ---------------------------------------------------------------------------
// 6) out = (1-beta)*X + beta*(X @ W)   -- tf32 MMA for X@W only.
__global__ __launch_bounds__(256, 2)
void k_gemm_tf32(const float* __restrict__ W,
                 float* __restrict__ out,
                 const float* __restrict__ lamda_p,
                 const void* __restrict__ l_p, int M)
{
    __shared__ float Xs[128][36];
    __shared__ float Bs[32][132];

    const int tid   = threadIdx.x;
    const int warp  = tid >> 5;
    const int lane  = tid & 31;
    const int gid   = lane >> 2;
    const int ln4   = lane & 3;
    const int warpM = warp & 3;
    const int warpN = warp >> 2;
    const int blockRow = blockIdx.x * 128;
    const int blockCol = blockIdx.y * 128;

    float acc[2][8][4];
#pragma unroll
    for (int a = 0; a < 2; a++)
#pragma unroll
        for (int b = 0; b < 8; b++)
#pragma unroll
            for (int c = 0; c < 4; c++) acc[a][b][c] = 0.0f;

    for (int k0 = 0; k0 < F; k0 += 32) {
#pragma unroll
        for (int i = 0; i < 4; i++) {
            int idx = tid + i * 256;
            int r = idx >> 3, c4 = idx & 7;
            int grow = blockRow + r;
            float4 v = make_float4(0.f, 0.f, 0.f, 0.f);
            if (grow < M)
                v = *reinterpret_cast<const float4*>(&g_X[(size_t)grow * F + k0 + c4 * 4]);
            *reinterpret_cast<float4*>(&Xs[r][c4 * 4]) = v;
        }
#pragma unroll
        for (int i = 0; i < 4; i++) {
            int idx = tid + i * 256;
            int r = idx >> 5, c4 = idx & 31;
            float4 v = *reinterpret_cast<const float4*>(
                &W[(size_t)(k0 + r) * F + blockCol + c4 * 4]);
            *reinterpret_cast<float4*>(&Bs[r][c4 * 4]) = v;
        }
        __syncthreads();

#pragma unroll
        for (int ks = 0; ks < 32; ks += 8) {
            uint32_t afr[2][4];
#pragma unroll
            for (int mt = 0; mt < 2; mt++) {
                int r0 = warpM * 32 + mt * 16 + gid;
                afr[mt][0] = __float_as_uint(Xs[r0][ks + ln4]);
                afr[mt][1] = __float_as_uint(Xs[r0 + 8][ks + ln4]);
                afr[mt][2] = __float_as_uint(Xs[r0][ks + ln4 + 4]);
                afr[mt][3] = __float_as_uint(Xs[r0 + 8][ks + ln4 + 4]);
            }
#pragma unroll
            for (int nt = 0; nt < 8; nt++) {
                int c0 = warpN * 64 + nt * 8 + gid;
                uint32_t b0 = __float_as_uint(Bs[ks + ln4][c0]);
                uint32_t b1 = __float_as_uint(Bs[ks + ln4 + 4][c0]);
#pragma unroll
                for (int mt = 0; mt < 2; mt++) {
                    asm volatile(
                        "mma.sync.aligned.m16n8k8.row.col.f32.tf32.tf32.f32 "
                        "{%0,%1,%2,%3}, {%4,%5,%6,%7}, {%8,%9}, {%0,%1,%2,%3};\n"
                        : "+f"(acc[mt][nt][0]), "+f"(acc[mt][nt][1]),
                          "+f"(acc[mt][nt][2]), "+f"(acc[mt][nt][3])
                        : "r"(afr[mt][0]), "r"(afr[mt][1]),
                          "r"(afr[mt][2]), "r"(afr[mt][3]),
                          "r"(b0), "r"(b1));
                }
            }
        }
        __syncthreads();
    }

    float lam = __ldg(lamda_p);
    int   li  = *reinterpret_cast<const int*>(l_p);
    float lf  = (li > 0 && li < (1 << 20)) ? (float)li
                                           : *reinterpret_cast<const float*>(l_p);
    float beta = logf(lam / lf + 1.0f);
    float ob   = 1.0f - beta;

#pragma unroll
    for (int mt = 0; mt < 2; mt++) {
#pragma unroll
        for (int half = 0; half < 2; half++) {
            int row = blockRow + warpM * 32 + mt * 16 + gid + half * 8;
            if (row >= M) continue;
#pragma unroll
            for (int nt = 0; nt < 8; nt++) {
                int col = blockCol + warpN * 64 + nt * 8 + 2 * ln4;
                float2 xv = *reinterpret_cast<const float2*>(&g_X[(size_t)row * F + col]);
                float2 o;
                o.x = ob * xv.x + beta * acc[mt][nt][half * 2 + 0];
                o.y = ob * xv.y + beta * acc[mt][nt][half * 2 + 1];
                *reinterpret_cast<float2*>(&out[(size_t)row * F + col]) = o;
            }
        }
    }
}

// ---------------------------------------------------------------------------
extern "C" void kernel_launch(void* const* d_in, const int* in_sizes, int n_in,
                              void* d_out, int out_size) {
    const float* H     = (const float*)d_in[0];
    const int*   ei    = (const int*)d_in[1];
    const float* H0    = (const float*)d_in[2];
    const float* W     = (const float*)d_in[3];
    const float* lamda = (const float*)d_in[4];
    const float* alpha = (const float*)d_in[5];
    const void*  lp    = d_in[6];
    float* out = (float*)d_out;

    const int n = in_sizes[0] / F;   // 50000
    const int E = in_sizes[1] / 2;   // 800000
    const int nScanBlocks = (n + SCAN_CHUNK - 1) / SCAN_CHUNK;

    k_zero <<<(n + 255) / 256, 256>>>(n);
    k_count<<<(E + 255) / 256, 256>>>(ei, E);
    k_scan1<<<nScanBlocks, 256>>>(n);
    k_scan2<<<1, 32>>>(nScanBlocks);
    k_scan3<<<(n + 255) / 256, 256>>>(n);
    k_node <<<(n + 255) / 256, 256>>>(n);
    k_fill <<<(E + 255) / 256, 256>>>(ei, E);

    long long agg_threads = (long long)n * 32;
    k_agg<<<(int)((agg_threads + 255) / 256), 256>>>(H, H0, alpha, n);

    dim3 grid((n + 127) / 128, 2);
    k_gemm_tf32<<<grid, 256>>>(W, out, lamda, lp, n);
}

// round 4
// speedup vs baseline: 2.1098x; 1.0668x over previous
#include <cuda_runtime.h>
#include <math.h>
#include <stdint.h>

#define F 256
#define N_MAX 65536
#define E_CAP (1 << 20)
#define SCAN_CHUNK 2048

// Scratch (allocation-free rule: __device__ globals)
__device__ int   g_cnt[N_MAX];      // out-count per src (CSR)
__device__ int   g_degi[N_MAX];     // in-count per dst
__device__ int   g_off[N_MAX];      // CSR row offsets (exclusive scan of cnt)
__device__ int   g_cursor[N_MAX];   // fill cursors (init = off)
__device__ int   g_partial[64];     // scan block totals
__device__ int   g_partial2[64];    // scanned (exclusive) block totals
__device__ int   g_edst[E_CAP];     // CSR column (dst) indices
__device__ float g_dinv[N_MAX];
__device__ float g_invdeg[N_MAX];
__device__ float g_X[(size_t)N_MAX * F];

// ---------------------------------------------------------------------------
// cp.async helpers
__device__ __forceinline__ uint32_t smem_u32(const void* p) {
    return (uint32_t)__cvta_generic_to_shared(p);
}
__device__ __forceinline__ void cp_async16(uint32_t dst, const void* src, int src_bytes) {
    asm volatile("cp.async.cg.shared.global [%0], [%1], 16, %2;\n"
                 :: "r"(dst), "l"(src), "r"(src_bytes));
}
__device__ __forceinline__ void cp_commit() {
    asm volatile("cp.async.commit_group;\n" ::);
}
template <int N>
__device__ __forceinline__ void cp_wait() {
    asm volatile("cp.async.wait_group %0;\n" :: "n"(N));
}

// ---------------------------------------------------------------------------
// 1) histogram: out-count by src, in-count by dst (one edge pass)
__global__ void k_count(const int* __restrict__ ei, int E) {
    int e = blockIdx.x * blockDim.x + threadIdx.x;
    if (e < E) {
        atomicAdd(&g_cnt[ei[e]], 1);
        atomicAdd(&g_degi[ei[E + e]], 1);
    }
}

// ---------------------------------------------------------------------------
// 2) exclusive scan of g_cnt -> g_off   (chunks of 2048)
__global__ void k_scan1(int n) {
    const int tid = threadIdx.x;
    const int base = blockIdx.x * SCAN_CHUNK;
    int v[8]; int s = 0;
#pragma unroll
    for (int j = 0; j < 8; j++) {
        int idx = base + tid * 8 + j;
        int c = (idx < n) ? g_cnt[idx] : 0;
        v[j] = s; s += c;
    }
    __shared__ int sh[256];
    sh[tid] = s;
    __syncthreads();
    for (int o = 1; o < 256; o <<= 1) {
        int t = (tid >= o) ? sh[tid - o] : 0;
        __syncthreads();
        sh[tid] += t;
        __syncthreads();
    }
    int excl = sh[tid] - s;
#pragma unroll
    for (int j = 0; j < 8; j++) {
        int idx = base + tid * 8 + j;
        if (idx < n) g_off[idx] = excl + v[j];
    }
    if (tid == 255) g_partial[blockIdx.x] = sh[255];
}

__global__ void k_scan2(int nb) {   // nb <= 32
    int tid = threadIdx.x;
    int orig = (tid < nb) ? g_partial[tid] : 0;
    int x = orig;
#pragma unroll
    for (int o = 1; o < 32; o <<= 1) {
        int y = __shfl_up_sync(0xffffffffu, x, o);
        if (tid >= o) x += y;
    }
    if (tid < nb) g_partial2[tid] = x - orig;  // exclusive
}

// ---------------------------------------------------------------------------
// 3) fused: finalize offsets + cursors + per-node normalization
__global__ void k_scan3_node(int n) {
    int i = blockIdx.x * blockDim.x + threadIdx.x;
    if (i < n) {
        int off = g_off[i] + g_partial2[i / SCAN_CHUNK];
        g_off[i]    = off;
        g_cursor[i] = off;
        float d = (float)g_degi[i] + 1.0f;
        g_dinv[i]   = rsqrtf(d);
        g_invdeg[i] = 1.0f / d;
    }
}

// ---------------------------------------------------------------------------
// 4) CSR fill: bucket dst by src (cursor pre-initialized to offset)
__global__ void k_fill(const int* __restrict__ ei, int E) {
    int e = blockIdx.x * blockDim.x + threadIdx.x;
    if (e < E) {
        int pos = atomicAdd(&g_cursor[ei[e]], 1);
        g_edst[pos] = ei[E + e];
    }
}

// ---------------------------------------------------------------------------
// 5) fused aggregate + init: 2 warps per node (half row each), 4-edge unroll.
//    X[i] = (1-a)*(dinv[i]*sum_j H[j]*dinv[j] + H[i]*invdeg[i]) + a*H0[i]
__global__ __launch_bounds__(256)
void k_agg(const float* __restrict__ H,
           const float* __restrict__ H0,
           const float* __restrict__ alpha_p, int n)
{
    int gw   = (blockIdx.x * blockDim.x + threadIdx.x) >> 5;
    int node = gw >> 1;
    if (node >= n) return;
    int half = gw & 1;
    int lane = threadIdx.x & 31;
    int coff = half * 32 + lane;          // float4 column within the row (0..63)

    const int base = g_off[node];
    const int cnt  = g_cnt[node];

    const float4* H4 = reinterpret_cast<const float4*>(H);
    float4 acc = make_float4(0.f, 0.f, 0.f, 0.f);

    int e = 0;
    for (; e + 4 <= cnt; e += 4) {
        int d0 = __ldg(&g_edst[base + e]);
        int d1 = __ldg(&g_edst[base + e + 1]);
        int d2 = __ldg(&g_edst[base + e + 2]);
        int d3 = __ldg(&g_edst[base + e + 3]);
        float w0 = __ldg(&g_dinv[d0]);
        float w1 = __ldg(&g_dinv[d1]);
        float w2 = __ldg(&g_dinv[d2]);
        float w3 = __ldg(&g_dinv[d3]);
        float4 v0 = __ldg(H4 + (size_t)d0 * 64 + coff);
        float4 v1 = __ldg(H4 + (size_t)d1 * 64 + coff);
        float4 v2 = __ldg(H4 + (size_t)d2 * 64 + coff);
        float4 v3 = __ldg(H4 + (size_t)d3 * 64 + coff);
        acc.x += v0.x * w0 + v1.x * w1 + v2.x * w2 + v3.x * w3;
        acc.y += v0.y * w0 + v1.y * w1 + v2.y * w2 + v3.y * w3;
        acc.z += v0.z * w0 + v1.z * w1 + v2.z * w2 + v3.z * w3;
        acc.w += v0.w * w0 + v1.w * w1 + v2.w * w2 + v3.w * w3;
    }
    for (; e < cnt; e++) {
        int d0 = __ldg(&g_edst[base + e]);
        float w0 = __ldg(&g_dinv[d0]);
        float4 v0 = __ldg(H4 + (size_t)d0 * 64 + coff);
        acc.x += v0.x * w0; acc.y += v0.y * w0;
        acc.z += v0.z * w0; acc.w += v0.w * w0;
    }

    float a  = __ldg(alpha_p);
    float oa = 1.0f - a;
    float di = g_dinv[node];
    float id = g_invdeg[node];
    size_t ro = (size_t)node * 64 + coff;
    float4 h = __ldg(H4 + ro);
    float4 z = __ldg(reinterpret_cast<const float4*>(H0) + ro);
    float4 r;
    r.x = oa * (di * acc.x + h.x * id) + a * z.x;
    r.y = oa * (di * acc.y + h.y * id) + a * z.y;
    r.z = oa * (di * acc.z + h.z * id) + a * z.z;
    r.w = oa * (di * acc.w + h.w * id) + a * z.w;
    reinterpret_cast<float4*>(g_X)[ro] = r;
}

// ---------------------------------------------------------------------------
// 6) out = (1-beta)*X + beta*(X @ W)   -- tf32 MMA, cp.async double-buffered.
//    Block 128x128, 8 warps (4M x 2N), warp tile 32x64, BK=32, 2 stages.
#define XS_STRIDE 36
#define BS_STRIDE 132
#define XS_ELEMS (128 * XS_STRIDE)
#define BS_ELEMS (32 * BS_STRIDE)
#define STAGE_ELEMS (XS_ELEMS + BS_ELEMS)
#define GEMM_SMEM_BYTES (2 * STAGE_ELEMS * 4)

__global__ __launch_bounds__(256, 2)
void k_gemm_tf32(const float* __restrict__ W,
                 float* __restrict__ out,
                 const float* __restrict__ lamda_p,
                 const void* __restrict__ l_p, int M)
{
    extern __shared__ float smem[];
    float* Xs[2] = { smem, smem + STAGE_ELEMS };
    float* Bs[2] = { smem + XS_ELEMS, smem + STAGE_ELEMS + XS_ELEMS };

    const int tid   = threadIdx.x;
    const int warp  = tid >> 5;
    const int lane  = tid & 31;
    const int gid   = lane >> 2;
    const int ln4   = lane & 3;
    const int warpM = warp & 3;
    const int warpN = warp >> 2;
    const int blockRow = blockIdx.x * 128;
    const int blockCol = blockIdx.y * 128;

    float acc[2][8][4];
#pragma unroll
    for (int a = 0; a < 2; a++)
#pragma unroll
        for (int b = 0; b < 8; b++)
#pragma unroll
            for (int c = 0; c < 4; c++) acc[a][b][c] = 0.0f;

    // prefetch lambda: stage st, K-slice kt (k0 = kt*32)
    auto prefetch = [&](int kt, int st) {
        int k0 = kt * 32;
#pragma unroll
        for (int i = 0; i < 4; i++) {
            int idx = tid + i * 256;            // 0..1023
            int r = idx >> 3, c4 = idx & 7;     // A: 128 rows x 8 float4
            int grow = blockRow + r;
            uint32_t dst = smem_u32(&Xs[st][r * XS_STRIDE + c4 * 4]);
            const void* src = &g_X[(size_t)(grow < M ? grow : 0) * F + k0 + c4 * 4];
            cp_async16(dst, src, grow < M ? 16 : 0);
        }
#pragma unroll
        for (int i = 0; i < 4; i++) {
            int idx = tid + i * 256;
            int r = idx >> 5, c4 = idx & 31;    // B: 32 rows x 32 float4
            uint32_t dst = smem_u32(&Bs[st][r * BS_STRIDE + c4 * 4]);
            const void* src = &W[(size_t)(k0 + r) * F + blockCol + c4 * 4];
            cp_async16(dst, src, 16);
        }
        cp_commit();
    };

    prefetch(0, 0);

#pragma unroll
    for (int kt = 0; kt < 8; kt++) {
        int st = kt & 1;
        if (kt + 1 < 8) {
            prefetch(kt + 1, st ^ 1);
            cp_wait<1>();
        } else {
            cp_wait<0>();
        }
        __syncthreads();

        const float* Xc = Xs[st];
        const float* Bc = Bs[st];
#pragma unroll
        for (int ks = 0; ks < 32; ks += 8) {
            uint32_t afr[2][4];
#pragma unroll
            for (int mt = 0; mt < 2; mt++) {
                int r0 = warpM * 32 + mt * 16 + gid;
                afr[mt][0] = __float_as_uint(Xc[r0 * XS_STRIDE + ks + ln4]);
                afr[mt][1] = __float_as_uint(Xc[(r0 + 8) * XS_STRIDE + ks + ln4]);
                afr[mt][2] = __float_as_uint(Xc[r0 * XS_STRIDE + ks + ln4 + 4]);
                afr[mt][3] = __float_as_uint(Xc[(r0 + 8) * XS_STRIDE + ks + ln4 + 4]);
            }
#pragma unroll
            for (int nt = 0; nt < 8; nt++) {
                int c0 = warpN * 64 + nt * 8 + gid;
                uint32_t b0 = __float_as_uint(Bc[(ks + ln4) * BS_STRIDE + c0]);
                uint32_t b1 = __float_as_uint(Bc[(ks + ln4 + 4) * BS_STRIDE + c0]);
#pragma unroll
                for (int mt = 0; mt < 2; mt++) {
                    asm volatile(
                        "mma.sync.aligned.m16n8k8.row.col.f32.tf32.tf32.f32 "
                        "{%0,%1,%2,%3}, {%4,%5,%6,%7}, {%8,%9}, {%0,%1,%2,%3};\n"
                        : "+f"(acc[mt][nt][0]), "+f"(acc[mt][nt][1]),
                          "+f"(acc[mt][nt][2]), "+f"(acc[mt][nt][3])
                        : "r"(afr[mt][0]), "r"(afr[mt][1]),
                          "r"(afr[mt][2]), "r"(afr[mt][3]),
                          "r"(b0), "r"(b1));
                }
            }
        }
        __syncthreads();
    }

    float lam = __ldg(lamda_p);
    int   li  = *reinterpret_cast<const int*>(l_p);
    float lf  = (li > 0 && li < (1 << 20)) ? (float)li
                                           : *reinterpret_cast<const float*>(l_p);
    float beta = logf(lam / lf + 1.0f);
    float ob   = 1.0f - beta;

#pragma unroll
    for (int mt = 0; mt < 2; mt++) {
#pragma unroll
        for (int half = 0; half < 2; half++) {
            int row = blockRow + warpM * 32 + mt * 16 + gid + half * 8;
            if (row >= M) continue;
#pragma unroll
            for (int nt = 0; nt < 8; nt++) {
                int col = blockCol + warpN * 64 + nt * 8 + 2 * ln4;
                float2 xv = *reinterpret_cast<const float2*>(&g_X[(size_t)row * F + col]);
                float2 o;
                o.x = ob * xv.x + beta * acc[mt][nt][half * 2 + 0];
                o.y = ob * xv.y + beta * acc[mt][nt][half * 2 + 1];
                *reinterpret_cast<float2*>(&out[(size_t)row * F + col]) = o;
            }
        }
    }
}

// ---------------------------------------------------------------------------
extern "C" void kernel_launch(void* const* d_in, const int* in_sizes, int n_in,
                              void* d_out, int out_size) {
    const float* H     = (const float*)d_in[0];
    const int*   ei    = (const int*)d_in[1];
    const float* H0    = (const float*)d_in[2];
    const float* W     = (const float*)d_in[3];
    const float* lamda = (const float*)d_in[4];
    const float* alpha = (const float*)d_in[5];
    const void*  lp    = d_in[6];
    float* out = (float*)d_out;

    const int n = in_sizes[0] / F;   // 50000
    const int E = in_sizes[1] / 2;   // 800000
    const int nScanBlocks = (n + SCAN_CHUNK - 1) / SCAN_CHUNK;

    // zero counters via memset nodes (fewer kernel launches)
    void* p_cnt = nullptr; void* p_degi = nullptr;
    cudaGetSymbolAddress(&p_cnt, g_cnt);
    cudaGetSymbolAddress(&p_degi, g_degi);
    cudaMemsetAsync(p_cnt, 0, (size_t)n * sizeof(int), 0);
    cudaMemsetAsync(p_degi, 0, (size_t)n * sizeof(int), 0);

    cudaFuncSetAttribute(k_gemm_tf32,
                         cudaFuncAttributeMaxDynamicSharedMemorySize,
                         GEMM_SMEM_BYTES);

    k_count<<<(E + 255) / 256, 256>>>(ei, E);
    k_scan1<<<nScanBlocks, 256>>>(n);
    k_scan2<<<1, 32>>>(nScanBlocks);
    k_scan3_node<<<(n + 255) / 256, 256>>>(n);
    k_fill <<<(E + 255) / 256, 256>>>(ei, E);

    long long agg_threads = (long long)n * 64;   // 2 warps per node
    k_agg<<<(int)((agg_threads + 255) / 256), 256>>>(H, H0, alpha, n);

    dim3 grid((n + 127) / 128, 2);
    k_gemm_tf32<<<grid, 256, GEMM_SMEM_BYTES>>>(W, out, lamda, lp, n);
}

// round 5
// speedup vs baseline: 2.3369x; 1.1077x over previous
#include <cuda_runtime.h>
#include <math.h>
#include <stdint.h>

#define F 256
#define N_MAX 65536
#define E_CAP (1 << 20)
#define SCAN_CHUNK 2048

// Scratch (allocation-free rule: __device__ globals)
__device__ int   g_cnt[N_MAX];      // out-count per src (CSR)
__device__ int   g_degi[N_MAX];     // in-count per dst
__device__ int   g_off[N_MAX];      // CSR row offsets
__device__ int   g_cursor[N_MAX];   // fill cursors (init = off)
__device__ int   g_partial[64];
__device__ int   g_partial2[64];
__device__ int   g_edst[E_CAP];     // CSR column (dst) indices
__device__ float g_dinv[N_MAX];
__device__ float g_X[(size_t)N_MAX * F];
__device__ float g_Weff[F * F];     // (1-beta) I + beta W

// ---------------------------------------------------------------------------
// cp.async helpers
__device__ __forceinline__ uint32_t smem_u32(const void* p) {
    return (uint32_t)__cvta_generic_to_shared(p);
}
__device__ __forceinline__ void cp_async16(uint32_t dst, const void* src, int src_bytes) {
    asm volatile("cp.async.cg.shared.global [%0], [%1], 16, %2;\n"
                 :: "r"(dst), "l"(src), "r"(src_bytes));
}
__device__ __forceinline__ void cp_commit() {
    asm volatile("cp.async.commit_group;\n" ::);
}
template <int N>
__device__ __forceinline__ void cp_wait() {
    asm volatile("cp.async.wait_group %0;\n" :: "n"(N));
}

// ---------------------------------------------------------------------------
// Weff = (1-beta) I + beta W
__global__ void k_weff(const float* __restrict__ W,
                       const float* __restrict__ lamda_p,
                       const void* __restrict__ l_p) {
    float lam = __ldg(lamda_p);
    int   li  = *reinterpret_cast<const int*>(l_p);
    float lf  = (li > 0 && li < (1 << 20)) ? (float)li
                                           : *reinterpret_cast<const float*>(l_p);
    float beta = logf(lam / lf + 1.0f);
    int idx = blockIdx.x * blockDim.x + threadIdx.x;
    if (idx < F * F) {
        int r = idx >> 8, c = idx & 255;
        g_Weff[idx] = beta * W[idx] + ((r == c) ? (1.0f - beta) : 0.0f);
    }
}

// ---------------------------------------------------------------------------
// histogram: out-count by src, in-count by dst
__global__ void k_count(const int* __restrict__ ei, int E) {
    int e = blockIdx.x * blockDim.x + threadIdx.x;
    if (e < E) {
        atomicAdd(&g_cnt[ei[e]], 1);
        atomicAdd(&g_degi[ei[E + e]], 1);
    }
}

// ---------------------------------------------------------------------------
// exclusive scan of g_cnt -> g_off
__global__ void k_scan1(int n) {
    const int tid = threadIdx.x;
    const int base = blockIdx.x * SCAN_CHUNK;
    int v[8]; int s = 0;
#pragma unroll
    for (int j = 0; j < 8; j++) {
        int idx = base + tid * 8 + j;
        int c = (idx < n) ? g_cnt[idx] : 0;
        v[j] = s; s += c;
    }
    __shared__ int sh[256];
    sh[tid] = s;
    __syncthreads();
    for (int o = 1; o < 256; o <<= 1) {
        int t = (tid >= o) ? sh[tid - o] : 0;
        __syncthreads();
        sh[tid] += t;
        __syncthreads();
    }
    int excl = sh[tid] - s;
#pragma unroll
    for (int j = 0; j < 8; j++) {
        int idx = base + tid * 8 + j;
        if (idx < n) g_off[idx] = excl + v[j];
    }
    if (tid == 255) g_partial[blockIdx.x] = sh[255];
}

__global__ void k_scan2(int nb) {
    int tid = threadIdx.x;
    int orig = (tid < nb) ? g_partial[tid] : 0;
    int x = orig;
#pragma unroll
    for (int o = 1; o < 32; o <<= 1) {
        int y = __shfl_up_sync(0xffffffffu, x, o);
        if (tid >= o) x += y;
    }
    if (tid < nb) g_partial2[tid] = x - orig;
}

// fused: finalize offsets + cursors + per-node normalization
__global__ void k_scan3_node(int n) {
    int i = blockIdx.x * blockDim.x + threadIdx.x;
    if (i < n) {
        int off = g_off[i] + g_partial2[i / SCAN_CHUNK];
        g_off[i]    = off;
        g_cursor[i] = off;
        float d = (float)g_degi[i] + 1.0f;
        g_dinv[i] = rsqrtf(d);
    }
}

// ---------------------------------------------------------------------------
// CSR fill
__global__ void k_fill(const int* __restrict__ ei, int E) {
    int e = blockIdx.x * blockDim.x + threadIdx.x;
    if (e < E) {
        int pos = atomicAdd(&g_cursor[ei[e]], 1);
        g_edst[pos] = ei[E + e];
    }
}

// ---------------------------------------------------------------------------
// fused aggregate + init: 2 warps per node, 4-edge unroll.
// X[i] = (1-a)*(dinv[i]*sum_j H[j]*dinv[j] + H[i]*dinv[i]^2) + a*H0[i]
__global__ __launch_bounds__(256)
void k_agg(const float* __restrict__ H,
           const float* __restrict__ H0,
           const float* __restrict__ alpha_p, int n)
{
    int gw   = (blockIdx.x * blockDim.x + threadIdx.x) >> 5;
    int node = gw >> 1;
    if (node >= n) return;
    int half = gw & 1;
    int lane = threadIdx.x & 31;
    int coff = half * 32 + lane;

    const int base = g_off[node];
    const int cnt  = g_cnt[node];

    const float4* H4 = reinterpret_cast<const float4*>(H);
    float4 acc = make_float4(0.f, 0.f, 0.f, 0.f);

    int e = 0;
    for (; e + 4 <= cnt; e += 4) {
        int d0 = __ldg(&g_edst[base + e]);
        int d1 = __ldg(&g_edst[base + e + 1]);
        int d2 = __ldg(&g_edst[base + e + 2]);
        int d3 = __ldg(&g_edst[base + e + 3]);
        float w0 = __ldg(&g_dinv[d0]);
        float w1 = __ldg(&g_dinv[d1]);
        float w2 = __ldg(&g_dinv[d2]);
        float w3 = __ldg(&g_dinv[d3]);
        float4 v0 = __ldg(H4 + (size_t)d0 * 64 + coff);
        float4 v1 = __ldg(H4 + (size_t)d1 * 64 + coff);
        float4 v2 = __ldg(H4 + (size_t)d2 * 64 + coff);
        float4 v3 = __ldg(H4 + (size_t)d3 * 64 + coff);
        acc.x += v0.x * w0 + v1.x * w1 + v2.x * w2 + v3.x * w3;
        acc.y += v0.y * w0 + v1.y * w1 + v2.y * w2 + v3.y * w3;
        acc.z += v0.z * w0 + v1.z * w1 + v2.z * w2 + v3.z * w3;
        acc.w += v0.w * w0 + v1.w * w1 + v2.w * w2 + v3.w * w3;
    }
    for (; e < cnt; e++) {
        int d0 = __ldg(&g_edst[base + e]);
        float w0 = __ldg(&g_dinv[d0]);
        float4 v0 = __ldg(H4 + (size_t)d0 * 64 + coff);
        acc.x += v0.x * w0; acc.y += v0.y * w0;
        acc.z += v0.z * w0; acc.w += v0.w * w0;
    }

    float a  = __ldg(alpha_p);
    float oa = 1.0f - a;
    float di = g_dinv[node];
    float id = di * di;
    size_t ro = (size_t)node * 64 + coff;
    float4 h = __ldg(H4 + ro);
    float4 z = __ldg(reinterpret_cast<const float4*>(H0) + ro);
    float4 r;
    r.x = oa * (di * acc.x + h.x * id) + a * z.x;
    r.y = oa * (di * acc.y + h.y * id) + a * z.y;
    r.z = oa * (di * acc.z + h.z * id) + a * z.z;
    r.w = oa * (di * acc.w + h.w * id) + a * z.w;
    reinterpret_cast<float4*>(g_X)[ro] = r;
}

// ---------------------------------------------------------------------------
// out = X @ Weff, tf32 MMA, cp.async double-buffered.
// Block 128x256 (full N), 512 threads = 16 warps (4M x 4N), warp tile 32x64.
#define XS_STRIDE 36
#define BS_STRIDE 264
#define XS_ELEMS (128 * XS_STRIDE)
#define BS_ELEMS (32 * BS_STRIDE)
#define STAGE_ELEMS (XS_ELEMS + BS_ELEMS)
#define GEMM_SMEM_BYTES (2 * STAGE_ELEMS * 4)

__global__ __launch_bounds__(512, 1)
void k_gemm_tf32(float* __restrict__ out, int M)
{
    extern __shared__ float smem[];
    float* Xs[2] = { smem, smem + STAGE_ELEMS };
    float* Bs[2] = { smem + XS_ELEMS, smem + STAGE_ELEMS + XS_ELEMS };

    const int tid   = threadIdx.x;
    const int warp  = tid >> 5;
    const int lane  = tid & 31;
    const int gid   = lane >> 2;
    const int ln4   = lane & 3;
    const int warpM = warp & 3;   // 0..3
    const int warpN = warp >> 2;  // 0..3
    const int blockRow = blockIdx.x * 128;

    float acc[2][8][4];
#pragma unroll
    for (int a = 0; a < 2; a++)
#pragma unroll
        for (int b = 0; b < 8; b++)
#pragma unroll
            for (int c = 0; c < 4; c++) acc[a][b][c] = 0.0f;

    auto prefetch = [&](int kt, int st) {
        int k0 = kt * 32;
#pragma unroll
        for (int i = 0; i < 2; i++) {          // A: 128x8 float4 = 1024
            int idx = tid + i * 512;
            int r = idx >> 3, c4 = idx & 7;
            int grow = blockRow + r;
            uint32_t dst = smem_u32(&Xs[st][r * XS_STRIDE + c4 * 4]);
            const void* src = &g_X[(size_t)(grow < M ? grow : 0) * F + k0 + c4 * 4];
            cp_async16(dst, src, grow < M ? 16 : 0);
        }
#pragma unroll
        for (int i = 0; i < 4; i++) {          // B: 32x64 float4 = 2048
            int idx = tid + i * 512;
            int r = idx >> 6, c4 = idx & 63;
            uint32_t dst = smem_u32(&Bs[st][r * BS_STRIDE + c4 * 4]);
            const void* src = &g_Weff[(size_t)(k0 + r) * F + c4 * 4];
            cp_async16(dst, src, 16);
        }
        cp_commit();
    };

    prefetch(0, 0);

#pragma unroll
    for (int kt = 0; kt < 8; kt++) {
        int st = kt & 1;
        if (kt + 1 < 8) {
            prefetch(kt + 1, st ^ 1);
            cp_wait<1>();
        } else {
            cp_wait<0>();
        }
        __syncthreads();

        const float* Xc = Xs[st];
        const float* Bc = Bs[st];
#pragma unroll
        for (int ks = 0; ks < 32; ks += 8) {
            uint32_t afr[2][4];
#pragma unroll
            for (int mt = 0; mt < 2; mt++) {
                int r0 = warpM * 32 + mt * 16 + gid;
                afr[mt][0] = __float_as_uint(Xc[r0 * XS_STRIDE + ks + ln4]);
                afr[mt][1] = __float_as_uint(Xc[(r0 + 8) * XS_STRIDE + ks + ln4]);
                afr[mt][2] = __float_as_uint(Xc[r0 * XS_STRIDE + ks + ln4 + 4]);
                afr[mt][3] = __float_as_uint(Xc[(r0 + 8) * XS_STRIDE + ks + ln4 + 4]);
            }
#pragma unroll
            for (int nt = 0; nt < 8; nt++) {
                int c0 = warpN * 64 + nt * 8 + gid;
                uint32_t b0 = __float_as_uint(Bc[(ks + ln4) * BS_STRIDE + c0]);
                uint32_t b1 = __float_as_uint(Bc[(ks + ln4 + 4) * BS_STRIDE + c0]);
#pragma unroll
                for (int mt = 0; mt < 2; mt++) {
                    asm volatile(
                        "mma.sync.aligned.m16n8k8.row.col.f32.tf32.tf32.f32 "
                        "{%0,%1,%2,%3}, {%4,%5,%6,%7}, {%8,%9}, {%0,%1,%2,%3};\n"
                        : "+f"(acc[mt][nt][0]), "+f"(acc[mt][nt][1]),
                          "+f"(acc[mt][nt][2]), "+f"(acc[mt][nt][3])
                        : "r"(afr[mt][0]), "r"(afr[mt][1]),
                          "r"(afr[mt][2]), "r"(afr[mt][3]),
                          "r"(b0), "r"(b1));
                }
            }
        }
        __syncthreads();
    }

    // epilogue: out = acc (mix folded into Weff)
#pragma unroll
    for (int mt = 0; mt < 2; mt++) {
#pragma unroll
        for (int half = 0; half < 2; half++) {
            int row = blockRow + warpM * 32 + mt * 16 + gid + half * 8;
            if (row >= M) continue;
#pragma unroll
            for (int nt = 0; nt < 8; nt++) {
                int col = warpN * 64 + nt * 8 + 2 * ln4;
                float2 o = make_float2(acc[mt][nt][half * 2 + 0],
                                       acc[mt][nt][half * 2 + 1]);
                *reinterpret_cast<float2*>(&out[(size_t)row * F + col]) = o;
            }
        }
    }
}

// ---------------------------------------------------------------------------
extern "C" void kernel_launch(void* const* d_in, const int* in_sizes, int n_in,
                              void* d_out, int out_size) {
    const float* H     = (const float*)d_in[0];
    const int*   ei    = (const int*)d_in[1];
    const float* H0    = (const float*)d_in[2];
    const float* W     = (const float*)d_in[3];
    const float* lamda = (const float*)d_in[4];
    const float* alpha = (const float*)d_in[5];
    const void*  lp    = d_in[6];
    float* out = (float*)d_out;

    const int n = in_sizes[0] / F;   // 50000
    const int E = in_sizes[1] / 2;   // 800000
    const int nScanBlocks = (n + SCAN_CHUNK - 1) / SCAN_CHUNK;

    void* p_cnt = nullptr; void* p_degi = nullptr;
    cudaGetSymbolAddress(&p_cnt, g_cnt);
    cudaGetSymbolAddress(&p_degi, g_degi);
    cudaMemsetAsync(p_cnt, 0, (size_t)n * sizeof(int), 0);
    cudaMemsetAsync(p_degi, 0, (size_t)n * sizeof(int), 0);

    cudaFuncSetAttribute(k_gemm_tf32,
                         cudaFuncAttributeMaxDynamicSharedMemorySize,
                         GEMM_SMEM_BYTES);

    k_weff <<<(F * F + 255) / 256, 256>>>(W, lamda, lp);
    k_count<<<(E + 255) / 256, 256>>>(ei, E);
    k_scan1<<<nScanBlocks, 256>>>(n);
    k_scan2<<<1, 32>>>(nScanBlocks);
    k_scan3_node<<<(n + 255) / 256, 256>>>(n);
    k_fill <<<(E + 255) / 256, 256>>>(ei, E);

    long long agg_threads = (long long)n * 64;   // 2 warps per node
    k_agg<<<(int)((agg_threads + 255) / 256), 256>>>(H, H0, alpha, n);

    k_gemm_tf32<<<(n + 127) / 128, 512, GEMM_SMEM_BYTES>>>(out, n);
}